// round 1
// baseline (speedup 1.0000x reference)
#include <cuda_runtime.h>

// Fused capsule layer: per-input-capsule 3x3 SAME conv (votes) + 3-iteration
// dynamic routing, all in one kernel. Routing is per-pixel-local, so votes
// for a 32-pixel tile live entirely in shared memory (no global scratch).
//
// Shapes:
//   x   [B=32, H=32, W=32, IN_CAPS=8, IN_F=16]   fp32
//   W   [8, 3, 3, 16, 128]                        fp32 (128 = 8 caps * 16 filt)
//   b   [1, 1, 8, 16]                             fp32
//   out [32, 32, 32, 8, 16]                       fp32

#define TH 4
#define TW 8
#define NPX 32            // pixels per block tile
#define IN_CAPS 8
#define CF 128            // NUM_CAPSULE * FILTERS
#define EPS_SQ 1e-7f

#define SX_ROWS 6         // TH + 2 halo
#define SX_COLS 10        // TW + 2 halo
#define SX_SIZE (SX_ROWS * SX_COLS * 128)   // 7680 floats
#define SV_SIZE (NPX * IN_CAPS * CF)        // 32768 floats
#define SW_SIZE (2 * 16 * CF)               // 4096 floats (double buffer)
#define SMEM_FLOATS (SX_SIZE + SV_SIZE + SW_SIZE)
#define SMEM_BYTES  (SMEM_FLOATS * 4)       // 178176 B

extern __shared__ float smem[];

__global__ __launch_bounds__(256, 1)
void caps_fused_kernel(const float* __restrict__ x,
                       const float* __restrict__ Wt,
                       const float* __restrict__ bias,
                       float* __restrict__ out)
{
    float* s_x = smem;                 // [6][10][128]
    float* s_v = smem + SX_SIZE;       // [32 px][8 i][128 cf]
    float* s_w = s_v + SV_SIZE;        // [2][16][128]

    const int t  = threadIdx.x;
    const int b  = blockIdx.z;
    const int h0 = blockIdx.y * TH;
    const int w0 = blockIdx.x * TW;

    // ---------------- load x tile with halo (zero-pad SAME borders) ---------
    // 7680 floats = 1920 float4; 256 threads
    {
        const float4* xg = reinterpret_cast<const float4*>(x);
        float4* sx4 = reinterpret_cast<float4*>(s_x);
        #pragma unroll
        for (int e4 = t; e4 < SX_SIZE / 4; e4 += 256) {
            int row = e4 / (SX_COLS * 32);
            int rem = e4 % (SX_COLS * 32);
            int col = rem / 32;
            int c4  = rem % 32;
            int hh = h0 + row - 1;
            int ww = w0 + col - 1;
            float4 v = make_float4(0.f, 0.f, 0.f, 0.f);
            if (hh >= 0 && hh < 32 && ww >= 0 && ww < 32)
                v = xg[(((b * 32 + hh) * 32 + ww) * 128) / 4 + c4];
            sx4[e4] = v;
        }
    }

    const int cfg = t & 31;   // cf group: covers cf = cfg*4 .. cfg*4+3
    const int lx  = t >> 5;   // local x column (0..7); whole warp shares lx

    const float4* Wg = reinterpret_cast<const float4*>(Wt);
    float4* sw4w = reinterpret_cast<float4*>(s_w);

    // ---------------- conv phase: 8 GEMMs (M=32px, K=144, N=128) ------------
    for (int i = 0; i < IN_CAPS; i++) {
        float acc[4][4];
        #pragma unroll
        for (int a = 0; a < 4; a++)
            #pragma unroll
            for (int j = 0; j < 4; j++) acc[a][j] = 0.f;

        for (int k = 0; k < 9; k++) {
            if (k == 0) {
                // guard s_w buffer 0 against previous i's k=8 compute
                __syncthreads();
                int base4 = (i * 9 + 0) * 512;   // chunk = 2048 floats = 512 f4
                sw4w[t]       = Wg[base4 + t];
                sw4w[t + 256] = Wg[base4 + t + 256];
            }
            __syncthreads();   // stage(k) visible; compute(k-1) done
            if (k + 1 < 9) {
                int base4 = (i * 9 + (k + 1)) * 512;
                int boff  = ((k + 1) & 1) * 512;
                sw4w[boff + t]       = Wg[base4 + t];
                sw4w[boff + t + 256] = Wg[base4 + t + 256];
            }
            const int ky = k / 3, kx = k % 3;
            const float4* sw4 = reinterpret_cast<const float4*>(s_w) + (k & 1) * 512;
            const float* sxb = s_x + (ky * SX_COLS + lx + kx) * 128 + i * 16;
            #pragma unroll
            for (int fin = 0; fin < 16; fin++) {
                float4 wv = sw4[fin * 32 + cfg];
                #pragma unroll
                for (int ly = 0; ly < 4; ly++) {
                    float xv = sxb[ly * (SX_COLS * 128) + fin];
                    acc[ly][0] += xv * wv.x;
                    acc[ly][1] += xv * wv.y;
                    acc[ly][2] += xv * wv.z;
                    acc[ly][3] += xv * wv.w;
                }
            }
        }
        // write votes to smem
        float4* sv4 = reinterpret_cast<float4*>(s_v);
        #pragma unroll
        for (int ly = 0; ly < 4; ly++) {
            int px = ly * 8 + lx;
            sv4[(px * IN_CAPS + i) * 32 + cfg] =
                make_float4(acc[ly][0], acc[ly][1], acc[ly][2], acc[ly][3]);
        }
    }
    __syncthreads();

    // ---------------- routing phase: one warp per pixel ---------------------
    // lane = c*4 + fq;  lane owns (output capsule c, filters fq*4..fq*4+3)
    const int wid  = t >> 5;
    const int lane = t & 31;
    const float4 bv = reinterpret_cast<const float4*>(bias)[lane];
    const float4* sv4 = reinterpret_cast<const float4*>(s_v);

    for (int q = 0; q < 4; q++) {
        const int px  = wid * 4 + q;
        const int ly  = px >> 3;
        const int lxp = px & 7;

        float4 v[8];
        #pragma unroll
        for (int i = 0; i < 8; i++)
            v[i] = sv4[(px * IN_CAPS + i) * 32 + lane];

        float logit[8];
        #pragma unroll
        for (int i = 0; i < 8; i++) logit[i] = 0.f;

        float4 act = make_float4(0.f, 0.f, 0.f, 0.f);

        #pragma unroll
        for (int r = 0; r < 3; r++) {
            // softmax over output capsules c (lanes differ in bits 2..4)
            float route[8];
            #pragma unroll
            for (int i = 0; i < 8; i++) {
                float m = logit[i];
                m = fmaxf(m, __shfl_xor_sync(0xffffffffu, m, 4));
                m = fmaxf(m, __shfl_xor_sync(0xffffffffu, m, 8));
                m = fmaxf(m, __shfl_xor_sync(0xffffffffu, m, 16));
                float e = __expf(logit[i] - m);
                float s = e;
                s += __shfl_xor_sync(0xffffffffu, s, 4);
                s += __shfl_xor_sync(0xffffffffu, s, 8);
                s += __shfl_xor_sync(0xffffffffu, s, 16);
                route[i] = e / s;
            }
            // preactivate = sum_i route[i]*votes[i] + bias
            float4 pre = bv;
            #pragma unroll
            for (int i = 0; i < 8; i++) {
                pre.x += route[i] * v[i].x;
                pre.y += route[i] * v[i].y;
                pre.z += route[i] * v[i].z;
                pre.w += route[i] * v[i].w;
            }
            // squash over f (16 values across the 4 fq lanes of this c)
            float s2 = pre.x * pre.x + pre.y * pre.y + pre.z * pre.z + pre.w * pre.w;
            s2 += __shfl_xor_sync(0xffffffffu, s2, 1);
            s2 += __shfl_xor_sync(0xffffffffu, s2, 2);
            float scale = s2 / (1.f + s2) * rsqrtf(s2 + EPS_SQ);
            act.x = scale * pre.x;
            act.y = scale * pre.y;
            act.z = scale * pre.z;
            act.w = scale * pre.w;
            if (r < 2) {
                #pragma unroll
                for (int i = 0; i < 8; i++) {
                    float d = v[i].x * act.x + v[i].y * act.y +
                              v[i].z * act.z + v[i].w * act.w;
                    d += __shfl_xor_sync(0xffffffffu, d, 1);
                    d += __shfl_xor_sync(0xffffffffu, d, 2);
                    logit[i] += d;
                }
            }
        }

        const int hh = h0 + ly, ww = w0 + lxp;
        reinterpret_cast<float4*>(out)[(((b * 32 + hh) * 32 + ww) * 128) / 4 + lane] = act;
    }
}

extern "C" void kernel_launch(void* const* d_in, const int* in_sizes, int n_in,
                              void* d_out, int out_size)
{
    const float* x    = (const float*)d_in[0];
    const float* Wt   = (const float*)d_in[1];
    const float* bias = (const float*)d_in[2];
    float* out = (float*)d_out;

    (void)in_sizes; (void)n_in; (void)out_size;

    cudaFuncSetAttribute(caps_fused_kernel,
                         cudaFuncAttributeMaxDynamicSharedMemorySize, SMEM_BYTES);

    dim3 grid(32 / TW, 32 / TH, 32);   // (4, 8, 32)
    caps_fused_kernel<<<grid, 256, SMEM_BYTES>>>(x, Wt, bias, out);
}